// round 2
// baseline (speedup 1.0000x reference)
#include <cuda_runtime.h>
#include <stdint.h>
#include <math.h>

#define B_MAX    4
#define BINS     262144      // score_bits >> 12, scores in [0, 2)
#define CAND_CAP 8192
#define K_TOP    6000
#define OUT_N    1000
#define NMS_THR  0.7f

// ---------------- device scratch (static allocs only, per harness rules) ---
__device__ unsigned int        g_hist[B_MAX * BINS];
__device__ unsigned int        g_thr[B_MAX];
__device__ unsigned int        g_cnt[B_MAX];
__device__ unsigned long long  g_cand[B_MAX * CAND_CAP];

// ---------------- K1: histogram of fg-score bit prefixes --------------------
__global__ void hist_kernel(const float2* __restrict__ scores, int N) {
    int b = blockIdx.y;
    const float2* p = scores + (size_t)b * N;
    int base = blockIdx.x * (blockDim.x * 8);
#pragma unroll
    for (int k = 0; k < 8; k++) {
        int i = base + k * blockDim.x + threadIdx.x;
        if (i < N) {
            unsigned bin = __float_as_uint(p[i].y) >> 12;   // scores >= 0
            atomicAdd(&g_hist[b * BINS + bin], 1u);
        }
    }
}

// ---------------- K2: find per-batch bit threshold for top-K ----------------
__global__ void select_kernel() {
    int b = blockIdx.x, tid = threadIdx.x;          // 1024 threads
    const unsigned int* h = g_hist + (size_t)b * BINS;

    __shared__ unsigned int chunksum[1024];
    __shared__ unsigned int sc[1024];

    // warp-cooperative 256-bin chunk sums (coalesced loads)
    int warp = tid >> 5, lane = tid & 31;
    for (int c = warp; c < 1024; c += 32) {
        unsigned s = 0;
#pragma unroll
        for (int q = 0; q < 8; q++) s += h[c * 256 + q * 32 + lane];
        for (int off = 16; off; off >>= 1) s += __shfl_down_sync(0xffffffffu, s, off);
        if (lane == 0) chunksum[c] = s;
    }
    __syncthreads();

    // suffix order: thread t owns chunk (1023 - t); inclusive scan over t
    unsigned v = chunksum[1023 - tid];
    sc[tid] = v;
    __syncthreads();
    for (int off = 1; off < 1024; off <<= 1) {
        unsigned add = (tid >= off) ? sc[tid - off] : 0u;
        __syncthreads();
        sc[tid] += add;
        __syncthreads();
    }
    unsigned incl = sc[tid], excl = incl - v;

    if (excl < K_TOP && incl >= K_TOP) {            // exactly one thread
        int c = 1023 - tid;
        unsigned cum = excl;
        unsigned T = 0;
        for (int bin = c * 256 + 255; bin >= c * 256; bin--) {
            cum += h[bin];
            if (cum >= K_TOP) { T = (unsigned)bin; break; }
        }
        g_thr[b] = T << 12;
        g_cnt[b] = 0u;
    }
    if (tid == 1023 && incl < K_TOP) { g_thr[b] = 0u; g_cnt[b] = 0u; }
}

// ---------------- K3: gather candidates above threshold ---------------------
__global__ void gather_kernel(const float2* __restrict__ scores, int N) {
    int b = blockIdx.y;
    unsigned thr = g_thr[b];
    const float2* p = scores + (size_t)b * N;
    int base = blockIdx.x * (blockDim.x * 8);
#pragma unroll
    for (int k = 0; k < 8; k++) {
        int i = base + k * blockDim.x + threadIdx.x;
        if (i < N) {
            unsigned bits = __float_as_uint(p[i].y);
            if (bits >= thr) {
                unsigned pos = atomicAdd(&g_cnt[b], 1u);
                if (pos < CAND_CAP)
                    // key: score desc, then index asc (jax top_k tie rule)
                    g_cand[b * CAND_CAP + pos] =
                        ((unsigned long long)bits << 32) | (unsigned)(~(unsigned)i);
            }
        }
    }
}

// ---------------- K4: per-batch sort + box decode + greedy NMS --------------
extern __shared__ unsigned char s_raw[];

__global__ void __launch_bounds__(1024, 1)
sort_nms_kernel(const float4* __restrict__ deltas,
                const float4* __restrict__ anchors,
                float4* __restrict__ out, int N) {
    int b = blockIdx.x, tid = threadIdx.x;
    unsigned long long* keys = (unsigned long long*)s_raw;  // 64 KB
    float4* boxes = (float4*)s_raw;                         // 96 KB (aliased)

    unsigned n_cand = g_cnt[b];
    if (n_cand > CAND_CAP) n_cand = CAND_CAP;

    for (int i = tid; i < CAND_CAP; i += 1024)
        keys[i] = (i < (int)n_cand) ? g_cand[b * CAND_CAP + i] : 0ULL;
    __syncthreads();

    // bitonic sort, descending
    for (int k = 2; k <= CAND_CAP; k <<= 1) {
        for (int j = k >> 1; j > 0; j >>= 1) {
#pragma unroll
            for (int t = tid; t < CAND_CAP / 2; t += 1024) {
                int low = t & (j - 1);
                int i   = ((t ^ low) << 1) | low;
                int ix  = i | j;
                unsigned long long a = keys[i], c = keys[ix];
                bool sw = ((i & k) == 0) ? (a < c) : (a > c);
                if (sw) { keys[i] = c; keys[ix] = a; }
            }
            __syncthreads();
        }
    }

    // decode top-6000 boxes (read keys to regs, then overwrite smem as boxes)
    int n_top = (int)n_cand < K_TOP ? (int)n_cand : K_TOP;
    float4 mybox[6];
#pragma unroll
    for (int r = 0; r < 6; r++) {
        int jdx = r * 1024 + tid;
        float4 bx = make_float4(0.f, 0.f, 0.f, 0.f);
        if (jdx < n_top) {
            unsigned long long key = keys[jdx];
            unsigned idx = ~(unsigned)(key & 0xffffffffu);
            size_t off = (size_t)b * N + idx;
            float4 a = anchors[off];
            float4 d = deltas[off];
            float w  = a.z - a.x, h = a.w - a.y;
            float cx = a.x + 0.5f * w + d.x * 0.1f * w;
            float cy = a.y + 0.5f * h + d.y * 0.1f * h;
            float nw = w * expf(d.z * 0.2f);
            float nh = h * expf(d.w * 0.2f);
            bx.x = fminf(fmaxf(cx - 0.5f * nw, 0.f), 1.f);
            bx.y = fminf(fmaxf(cy - 0.5f * nh, 0.f), 1.f);
            bx.z = fminf(fmaxf(cx + 0.5f * nw, 0.f), 1.f);
            bx.w = fminf(fmaxf(cy + 0.5f * nh, 0.f), 1.f);
        }
        mybox[r] = bx;
    }
    __syncthreads();                 // all key reads done before alias write
#pragma unroll
    for (int r = 0; r < 6; r++) {
        int jdx = r * 1024 + tid;
        if (jdx < K_TOP) boxes[jdx] = mybox[r];
    }
    __syncthreads();

    // greedy NMS, early-terminate at OUT_N accepted.
    // Thread t holds accepted box #t in registers.
    float4 acc = make_float4(0.f, 0.f, 0.f, 0.f);
    float accArea = 0.f;
    int n_acc = 0;
    for (int i = 0; i < K_TOP && n_acc < OUT_N; i++) {
        float4 c = boxes[i];         // LDS.128 broadcast
        int pred = 0;
        if (tid < n_acc) {
            float areaC = (c.z - c.x) * (c.w - c.y);
            float ltx = fmaxf(acc.x, c.x), lty = fmaxf(acc.y, c.y);
            float rbx = fminf(acc.z, c.z), rby = fminf(acc.w, c.w);
            float iw = fmaxf(rbx - ltx, 0.f), ih = fmaxf(rby - lty, 0.f);
            float inter = iw * ih;
            float iou = inter / (accArea + areaC - inter + 1e-12f);
            pred = (iou > NMS_THR);
        }
        int supp = __syncthreads_or(pred);   // single BAR.RED per candidate
        if (!supp) {
            if (tid == n_acc) { acc = c; accArea = (c.z - c.x) * (c.w - c.y); }
            n_acc++;                          // replicated, consistent
        }
    }

    if (tid < OUT_N)
        out[(size_t)b * OUT_N + tid] =
            (tid < n_acc) ? acc : make_float4(0.f, 0.f, 0.f, 0.f);
}

// ---------------- host launcher ---------------------------------------------
extern "C" void kernel_launch(void* const* d_in, const int* in_sizes, int n_in,
                              void* d_out, int out_size) {
    const float2* scores  = (const float2*)d_in[0];   // (B,N,2) f32
    const float4* deltas  = (const float4*)d_in[1];   // (B,N,4) f32
    const float4* anchors = (const float4*)d_in[2];   // (B,N,4) f32
    const int B = 4;
    const int N = in_sizes[0] / (B * 2);

    void* histPtr = nullptr;
    cudaGetSymbolAddress(&histPtr, g_hist);
    cudaMemsetAsync(histPtr, 0, sizeof(unsigned int) * (size_t)B_MAX * BINS);

    dim3 grid((N + 2047) / 2048, B);
    hist_kernel<<<grid, 256>>>(scores, N);
    select_kernel<<<B, 1024>>>();
    gather_kernel<<<grid, 256>>>(scores, N);

    cudaFuncSetAttribute(sort_nms_kernel,
                         cudaFuncAttributeMaxDynamicSharedMemorySize, 98304);
    sort_nms_kernel<<<B, 1024, 98304>>>(deltas, anchors, (float4*)d_out, N);
}

// round 3
// speedup vs baseline: 3.5665x; 3.5665x over previous
#include <cuda_runtime.h>
#include <stdint.h>
#include <math.h>

#define B_MAX    4
#define BINS     262144      // score_bits >> 12, scores in [0, 2)
#define CAND_CAP 8192
#define K_TOP    6000
#define OUT_N    1000
#define NMS_THR  0.7f
#define MSCAN    1024        // mask window: candidates covered by bitmask NMS
#define MWORDS   32          // MSCAN / 32
#define NBT      1024        // bin table span above threshold
#define BINSORT_CAP 512

// ---------------- device scratch (static, per harness rules) ----------------
__device__ unsigned int        g_hist[B_MAX * BINS];
__device__ unsigned int        g_thrbin[B_MAX];
__device__ unsigned int        g_ncand[B_MAX];
__device__ unsigned int        g_binstart[B_MAX * NBT];
__device__ unsigned int        g_binfill[B_MAX * NBT];
__device__ unsigned long long  g_cand[B_MAX * CAND_CAP];
__device__ float4              g_boxes[B_MAX * K_TOP];
__device__ unsigned int        g_mask[B_MAX * MSCAN * MWORDS];
__device__ unsigned int        g_rownz[B_MAX * MWORDS];

// ---------------- K1: histogram of fg-score bit prefixes --------------------
__global__ void hist_kernel(const float2* __restrict__ scores, int N) {
    int b = blockIdx.y;
    const float2* p = scores + (size_t)b * N;
    int base = blockIdx.x * (blockDim.x * 8);
#pragma unroll
    for (int k = 0; k < 8; k++) {
        int i = base + k * blockDim.x + threadIdx.x;
        if (i < N) {
            unsigned bin = __float_as_uint(p[i].y) >> 12;   // scores >= 0
            atomicAdd(&g_hist[b * BINS + bin], 1u);
        }
    }
}

// ------ K2: per-batch threshold bin + per-bin scatter offsets (top-down) ----
__global__ void select_kernel() {
    int b = blockIdx.x, tid = threadIdx.x;          // 1024 threads
    const unsigned int* h = g_hist + (size_t)b * BINS;

    __shared__ unsigned int chunksum[1024];
    __shared__ unsigned int sc[1024];
    __shared__ unsigned int s_T;

    int warp = tid >> 5, lane = tid & 31;
    for (int c = warp; c < 1024; c += 32) {
        unsigned s = 0;
#pragma unroll
        for (int q = 0; q < 8; q++) s += h[c * 256 + q * 32 + lane];
        for (int off = 16; off; off >>= 1) s += __shfl_down_sync(0xffffffffu, s, off);
        if (lane == 0) chunksum[c] = s;
    }
    __syncthreads();

    // suffix-ordered inclusive scan over 256-bin chunks
    unsigned v = chunksum[1023 - tid];
    sc[tid] = v;
    __syncthreads();
    for (int off = 1; off < 1024; off <<= 1) {
        unsigned add = (tid >= off) ? sc[tid - off] : 0u;
        __syncthreads();
        sc[tid] += add;
        __syncthreads();
    }
    unsigned incl = sc[tid], excl = incl - v;

    if (excl < K_TOP && incl >= K_TOP) {            // exactly one thread
        int c = 1023 - tid;
        unsigned cum = excl;
        unsigned T = 0;
        for (int bin = c * 256 + 255; bin >= c * 256; bin--) {
            cum += h[bin];
            if (cum >= K_TOP) { T = (unsigned)bin; break; }
        }
        s_T = T;
    }
    if (tid == 1023 && incl < K_TOP) s_T = 0;
    __syncthreads();

    unsigned T = s_T;
    if (tid == 0) g_thrbin[b] = T;

    // suffix sums over bins T..T+1023: start(bin) = count of bins > bin.
    // thread tid owns offset o = 1023 - tid.
    unsigned bin_rev = T + (unsigned)(1023 - tid);
    unsigned c_rev = (bin_rev < BINS) ? h[bin_rev] : 0u;
    sc[tid] = c_rev;
    __syncthreads();
    for (int off = 1; off < 1024; off <<= 1) {
        unsigned add = (tid >= off) ? sc[tid - off] : 0u;
        __syncthreads();
        sc[tid] += add;
        __syncthreads();
    }
    unsigned incl2 = sc[tid];
    g_binstart[b * NBT + (1023 - tid)] = incl2 - c_rev;
    if (tid == 1023) {
        unsigned n = incl2;
        g_ncand[b] = (n > CAND_CAP) ? CAND_CAP : n;
    }
}

// -------- K3: gather candidates, scattered into per-bin segments ------------
__global__ void gather_kernel(const float2* __restrict__ scores, int N) {
    int b = blockIdx.y;
    unsigned T = g_thrbin[b];
    const float2* p = scores + (size_t)b * N;
    int base = blockIdx.x * (blockDim.x * 8);
#pragma unroll
    for (int k = 0; k < 8; k++) {
        int i = base + k * blockDim.x + threadIdx.x;
        if (i < N) {
            unsigned bits = __float_as_uint(p[i].y);
            unsigned bin = bits >> 12;
            if (bin >= T) {
                unsigned o = bin - T;
                if (o < NBT) {
                    unsigned pos = g_binstart[b * NBT + o] +
                                   atomicAdd(&g_binfill[b * NBT + o], 1u);
                    if (pos < CAND_CAP)
                        // key: score desc, then index asc (jax top_k tie rule)
                        g_cand[(size_t)b * CAND_CAP + pos] =
                            ((unsigned long long)bits << 32) | (unsigned)(~(unsigned)i);
                }
            }
        }
    }
}

// -------- K4: per-bin rank sort (+ box decode for global rank < 6000) -------
__global__ void binsort_decode_kernel(const float4* __restrict__ deltas,
                                      const float4* __restrict__ anchors, int N) {
    int o = blockIdx.x, b = blockIdx.y, tid = threadIdx.x;   // 256 threads
    unsigned cnt = g_binfill[b * NBT + o];
    if (cnt == 0) return;
    if (cnt > BINSORT_CAP) cnt = BINSORT_CAP;
    unsigned start = g_binstart[b * NBT + o];
    if (start >= K_TOP) return;                    // whole bin beyond top-k

    __shared__ unsigned long long sk[BINSORT_CAP];
    for (int e = tid; e < (int)cnt; e += 256) {
        unsigned p = start + e;
        sk[e] = (p < CAND_CAP) ? g_cand[(size_t)b * CAND_CAP + p] : 0ULL;
    }
    __syncthreads();

    for (int e = tid; e < (int)cnt; e += 256) {
        unsigned long long key = sk[e];
        int rank = 0;
        for (int q = 0; q < (int)cnt; q++) rank += (sk[q] > key);
        unsigned pos = start + (unsigned)rank;     // global sorted rank
        if (pos < K_TOP) {
            unsigned idx = ~(unsigned)(key & 0xffffffffu);
            size_t off = (size_t)b * N + idx;
            float4 a = anchors[off];
            float4 d = deltas[off];
            float w  = a.z - a.x, h = a.w - a.y;
            float cx = a.x + 0.5f * w + d.x * 0.1f * w;
            float cy = a.y + 0.5f * h + d.y * 0.1f * h;
            float nw = w * expf(d.z * 0.2f);
            float nh = h * expf(d.w * 0.2f);
            float4 bx;
            bx.x = fminf(fmaxf(cx - 0.5f * nw, 0.f), 1.f);
            bx.y = fminf(fmaxf(cy - 0.5f * nh, 0.f), 1.f);
            bx.z = fminf(fmaxf(cx + 0.5f * nw, 0.f), 1.f);
            bx.w = fminf(fmaxf(cy + 0.5f * nh, 0.f), 1.f);
            g_boxes[(size_t)b * K_TOP + pos] = bx;
        }
    }
}

// -------- K5: pairwise suppression bitmask among first MSCAN candidates -----
__global__ void mask_kernel() {
    int w     = blockIdx.x;          // word 0..31 (candidates 32w..32w+31)
    int chunk = blockIdx.y;          // row chunk 0..7
    int b     = blockIdx.z;
    int tid   = threadIdx.x;         // 128 threads
    int i = chunk * 128 + tid;       // row (earlier candidate)

    __shared__ float4 bj[32];
    __shared__ float  aj[32];
    if (tid < 32) {
        float4 c = g_boxes[(size_t)b * K_TOP + w * 32 + tid];
        bj[tid] = c;
        aj[tid] = (c.z - c.x) * (c.w - c.y);
    }
    __syncthreads();

    float4 bi = g_boxes[(size_t)b * K_TOP + i];
    float ai = (bi.z - bi.x) * (bi.w - bi.y);

    unsigned word = 0;
    int j0 = i - w * 32 + 1;         // only j > i
    if (j0 < 0) j0 = 0;
    for (int jj = j0; jj < 32; jj++) {
        float4 c = bj[jj];
        float ltx = fmaxf(bi.x, c.x), lty = fmaxf(bi.y, c.y);
        float rbx = fminf(bi.z, c.z), rby = fminf(bi.w, c.w);
        float iw = fmaxf(rbx - ltx, 0.f), ih = fmaxf(rby - lty, 0.f);
        float inter = iw * ih;
        float iou = inter / (ai + aj[jj] - inter + 1e-12f);  // same expr as ref
        if (iou > NMS_THR) word |= (1u << jj);
    }
    g_mask[((size_t)b * MSCAN + i) * MWORDS + w] = word;
    if (word) atomicOr(&g_rownz[b * MWORDS + (i >> 5)], 1u << (i & 31));
}

// -------- K6: warp-serial bitmap NMS + fallback + output --------------------
__global__ void __launch_bounds__(1024, 1)
final_kernel(float4* __restrict__ out) {
    int b = blockIdx.x, tid = threadIdx.x;
    int lane = tid & 31;

    __shared__ int s_kept[OUT_N];
    __shared__ int s_nk, s_istart;

    if (tid < 32) {                  // warp 0: serial bitmap scan
        unsigned Rw  = 0;                              // suppressed bits, word=lane
        unsigned nzw = g_rownz[b * MWORDS + lane];     // row-nonzero bits, word=lane
        int nk = 0;
        int stop_i = MSCAN;
        for (int w = 0; w < MWORDS && nk < OUT_N; w++) {
            unsigned sup = __shfl_sync(0xffffffffu, Rw, w);
            unsigned nz  = __shfl_sync(0xffffffffu, nzw, w);
            for (int bb = 0; bb < 32; bb++) {
                int i = w * 32 + bb;
                if (!((sup >> bb) & 1u)) {
                    if (lane == 0) s_kept[nk] = i;
                    nk++;
                    if ((nz >> bb) & 1u) {
                        Rw |= g_mask[((size_t)b * MSCAN + i) * MWORDS + lane];
                        sup = __shfl_sync(0xffffffffu, Rw, w);
                    }
                    if (nk == OUT_N) { stop_i = i + 1; break; }
                }
            }
        }
        if (lane == 0) { s_nk = nk; s_istart = (nk == OUT_N) ? stop_i : MSCAN; }
    }
    __syncthreads();

    int nk = s_nk;
    int istart = s_istart;
    int n_top = min((int)g_ncand[b], K_TOP);

    if (nk < OUT_N && istart < n_top) {
        // fallback: continue with direct block NMS past the mask window
        float4 acc = make_float4(0.f, 0.f, 0.f, 0.f);
        float accA = 0.f;
        if (tid < nk) {
            acc = g_boxes[(size_t)b * K_TOP + s_kept[tid]];
            accA = (acc.z - acc.x) * (acc.w - acc.y);
        }
        for (int i = istart; i < n_top && nk < OUT_N; i++) {
            float4 c = g_boxes[(size_t)b * K_TOP + i];
            int pred = 0;
            if (tid < nk) {
                float areaC = (c.z - c.x) * (c.w - c.y);
                float ltx = fmaxf(acc.x, c.x), lty = fmaxf(acc.y, c.y);
                float rbx = fminf(acc.z, c.z), rby = fminf(acc.w, c.w);
                float iw = fmaxf(rbx - ltx, 0.f), ih = fmaxf(rby - lty, 0.f);
                float inter = iw * ih;
                float iou = inter / (accA + areaC - inter + 1e-12f);
                pred = (iou > NMS_THR);
            }
            int supp = __syncthreads_or(pred);
            if (!supp) {
                if (tid == nk) { acc = c; accA = (c.z - c.x) * (c.w - c.y); }
                if (tid == 0) s_kept[nk] = i;
                nk++;
            }
        }
        __syncthreads();
    }

    if (tid < OUT_N) {
        float4 v = make_float4(0.f, 0.f, 0.f, 0.f);
        if (tid < nk) v = g_boxes[(size_t)b * K_TOP + s_kept[tid]];
        out[(size_t)b * OUT_N + tid] = v;
    }
}

// ---------------- host launcher ---------------------------------------------
extern "C" void kernel_launch(void* const* d_in, const int* in_sizes, int n_in,
                              void* d_out, int out_size) {
    const float2* scores  = (const float2*)d_in[0];   // (B,N,2) f32
    const float4* deltas  = (const float4*)d_in[1];   // (B,N,4) f32
    const float4* anchors = (const float4*)d_in[2];   // (B,N,4) f32
    const int B = 4;
    const int N = in_sizes[0] / (B * 2);

    void *p0, *p1, *p2;
    cudaGetSymbolAddress(&p0, g_hist);
    cudaGetSymbolAddress(&p1, g_binfill);
    cudaGetSymbolAddress(&p2, g_rownz);
    cudaMemsetAsync(p0, 0, sizeof(unsigned) * (size_t)B_MAX * BINS);
    cudaMemsetAsync(p1, 0, sizeof(unsigned) * (size_t)B_MAX * NBT);
    cudaMemsetAsync(p2, 0, sizeof(unsigned) * (size_t)B_MAX * MWORDS);

    dim3 grid((N + 2047) / 2048, B);
    hist_kernel<<<grid, 256>>>(scores, N);
    select_kernel<<<B, 1024>>>();
    gather_kernel<<<grid, 256>>>(scores, N);
    binsort_decode_kernel<<<dim3(NBT, B), 256>>>(deltas, anchors, N);
    mask_kernel<<<dim3(MWORDS, MSCAN / 128, B), 128>>>();
    final_kernel<<<B, 1024>>>((float4*)d_out);
}

// round 5
// speedup vs baseline: 9.4218x; 2.6417x over previous
#include <cuda_runtime.h>
#include <stdint.h>
#include <math.h>

#define B_MAX    4
#define BINS     262144      // score_bits >> 12, scores in [0, 2)
#define CAND_CAP 8192
#define K_TOP    6000
#define OUT_N    1000
#define NMS_THR  0.7f
#define MSCAN    1024        // window covered by sparse pair NMS
#define NBT      1024        // bin table span above threshold
#define BINSORT_CAP 512
#define PAIR_CAP 2048

// ---------------- device scratch (static, per harness rules) ----------------
__device__ unsigned int        g_hist[B_MAX * BINS];
__device__ unsigned int        g_thrbin[B_MAX];
__device__ unsigned int        g_ncand[B_MAX];
__device__ unsigned int        g_binstart[B_MAX * NBT];
__device__ unsigned int        g_binfill[B_MAX * NBT];
__device__ unsigned long long  g_cand[B_MAX * CAND_CAP];
__device__ float4              g_boxes[B_MAX * K_TOP];
__device__ unsigned int        g_pairs[B_MAX * PAIR_CAP];
__device__ unsigned int        g_paircnt[B_MAX];

// ---------------- K1: histogram of fg-score bit prefixes --------------------
__global__ void hist_kernel(const float2* __restrict__ scores, int N) {
    int b = blockIdx.y;
    const float2* p = scores + (size_t)b * N;
    int base = blockIdx.x * (blockDim.x * 8);
#pragma unroll
    for (int k = 0; k < 8; k++) {
        int i = base + k * blockDim.x + threadIdx.x;
        if (i < N) {
            unsigned bin = __float_as_uint(p[i].y) >> 12;   // scores >= 0
            atomicAdd(&g_hist[b * BINS + bin], 1u);
        }
    }
}

// ------ K2: threshold bin (parallel) + per-bin scatter offsets + zeroing ----
__global__ void select_kernel() {
    int b = blockIdx.x, tid = threadIdx.x;          // 1024 threads
    const unsigned int* h = g_hist + (size_t)b * BINS;

    __shared__ unsigned int chunksum[1024];
    __shared__ unsigned int sc[1024];
    __shared__ unsigned int s_c, s_excl, s_T;

    // ---- A: 256-bin chunk sums (warp-cooperative, coalesced) ----
    int warp = tid >> 5, lane = tid & 31;
    for (int c = warp; c < 1024; c += 32) {
        unsigned s = 0;
#pragma unroll
        for (int q = 0; q < 8; q++) s += h[c * 256 + q * 32 + lane];
        for (int off = 16; off; off >>= 1) s += __shfl_down_sync(0xffffffffu, s, off);
        if (lane == 0) chunksum[c] = s;
    }
    __syncthreads();

    // ---- B: suffix-ordered inclusive scan over chunks; find crossing chunk
    unsigned v = chunksum[1023 - tid];
    sc[tid] = v;
    __syncthreads();
    for (int off = 1; off < 1024; off <<= 1) {
        unsigned add = (tid >= off) ? sc[tid - off] : 0u;
        __syncthreads();
        sc[tid] += add;
        __syncthreads();
    }
    unsigned incl = sc[tid], excl = incl - v;
    if (excl < K_TOP && incl >= K_TOP) { s_c = (unsigned)(1023 - tid); s_excl = excl; }
    if (tid == 1023 && incl < K_TOP) { s_c = 0xffffffffu; s_T = 0u; }
    __syncthreads();

    // ---- C: parallel suffix scan WITHIN crossing chunk (replaces serial walk)
    if (s_c != 0xffffffffu) {
        unsigned c = s_c, ex0 = s_excl;
        unsigned v2 = (tid < 256) ? h[c * 256 + 255 - tid] : 0u;
        sc[tid] = v2;
        __syncthreads();
        for (int off = 1; off < 1024; off <<= 1) {
            unsigned add = (tid >= off) ? sc[tid - off] : 0u;
            __syncthreads();
            sc[tid] += add;
            __syncthreads();
        }
        if (tid < 256) {
            unsigned i2 = ex0 + sc[tid], e2 = i2 - v2;
            if (e2 < K_TOP && i2 >= K_TOP) s_T = c * 256 + 255 - (unsigned)tid;
        }
        __syncthreads();
    }
    unsigned T = s_T;
    if (tid == 0) { g_thrbin[b] = T; g_paircnt[b] = 0u; }

    // ---- D: suffix sums over bins T..T+1023 → per-bin start offsets ----
    unsigned bin_rev = T + (unsigned)(1023 - tid);
    unsigned c_rev = (bin_rev < BINS) ? h[bin_rev] : 0u;
    __syncthreads();
    sc[tid] = c_rev;
    __syncthreads();
    for (int off = 1; off < 1024; off <<= 1) {
        unsigned add = (tid >= off) ? sc[tid - off] : 0u;
        __syncthreads();
        sc[tid] += add;
        __syncthreads();
    }
    unsigned incl2 = sc[tid];
    g_binstart[b * NBT + (1023 - tid)] = incl2 - c_rev;
    g_binfill[b * NBT + tid] = 0u;                  // folded memset
    if (tid == 1023) {
        unsigned n = incl2;
        g_ncand[b] = (n > CAND_CAP) ? CAND_CAP : n;
    }
}

// -------- K3: gather candidates, scattered into per-bin segments ------------
__global__ void gather_kernel(const float2* __restrict__ scores, int N) {
    int b = blockIdx.y;
    unsigned T = g_thrbin[b];
    const float2* p = scores + (size_t)b * N;
    int base = blockIdx.x * (blockDim.x * 8);
#pragma unroll
    for (int k = 0; k < 8; k++) {
        int i = base + k * blockDim.x + threadIdx.x;
        if (i < N) {
            unsigned bits = __float_as_uint(p[i].y);
            unsigned bin = bits >> 12;
            if (bin >= T) {
                unsigned o = bin - T;
                if (o < NBT) {
                    unsigned pos = g_binstart[b * NBT + o] +
                                   atomicAdd(&g_binfill[b * NBT + o], 1u);
                    if (pos < CAND_CAP)
                        // key: score desc, then index asc (jax top_k tie rule)
                        g_cand[(size_t)b * CAND_CAP + pos] =
                            ((unsigned long long)bits << 32) | (unsigned)(~(unsigned)i);
                }
            }
        }
    }
}

// -------- K4: per-bin rank sort (+ box decode for global rank < 6000) -------
__global__ void binsort_decode_kernel(const float4* __restrict__ deltas,
                                      const float4* __restrict__ anchors, int N) {
    int o = blockIdx.x, b = blockIdx.y, tid = threadIdx.x;   // 256 threads
    unsigned cnt = g_binfill[b * NBT + o];
    if (cnt == 0) return;
    if (cnt > BINSORT_CAP) cnt = BINSORT_CAP;
    unsigned start = g_binstart[b * NBT + o];
    if (start >= K_TOP) return;                    // whole bin beyond top-k

    __shared__ unsigned long long sk[BINSORT_CAP];
    for (int e = tid; e < (int)cnt; e += 256) {
        unsigned p = start + e;
        sk[e] = (p < CAND_CAP) ? g_cand[(size_t)b * CAND_CAP + p] : 0ULL;
    }
    __syncthreads();

    for (int e = tid; e < (int)cnt; e += 256) {
        unsigned long long key = sk[e];
        int rank = 0;
        for (int q = 0; q < (int)cnt; q++) rank += (sk[q] > key);
        unsigned pos = start + (unsigned)rank;     // global sorted rank
        if (pos < K_TOP) {
            unsigned idx = ~(unsigned)(key & 0xffffffffu);
            size_t off = (size_t)b * N + idx;
            float4 a = anchors[off];
            float4 d = deltas[off];
            float w  = a.z - a.x, h = a.w - a.y;
            float cx = a.x + 0.5f * w + d.x * 0.1f * w;
            float cy = a.y + 0.5f * h + d.y * 0.1f * h;
            float nw = w * expf(d.z * 0.2f);
            float nh = h * expf(d.w * 0.2f);
            float4 bx;
            bx.x = fminf(fmaxf(cx - 0.5f * nw, 0.f), 1.f);
            bx.y = fminf(fmaxf(cy - 0.5f * nh, 0.f), 1.f);
            bx.z = fminf(fmaxf(cx + 0.5f * nw, 0.f), 1.f);
            bx.w = fminf(fmaxf(cy + 0.5f * nh, 0.f), 1.f);
            g_boxes[(size_t)b * K_TOP + pos] = bx;
        }
    }
}

// -------- K5: sparse suppression pairs among first MSCAN candidates ---------
__global__ void pair_kernel() {
    int w     = blockIdx.x;          // cols 32w..32w+31
    int chunk = blockIdx.y;          // row chunk 0..7
    int b     = blockIdx.z;
    int tid   = threadIdx.x;         // 128 threads
    int i = chunk * 128 + tid;       // row (earlier candidate)

    int n_top = min((int)g_ncand[b], K_TOP);
    int win = min(n_top, MSCAN);

    __shared__ float4 bj[32];
    __shared__ float  aj[32];
    if (tid < 32) {
        int j = w * 32 + tid;
        float4 c = (j < win) ? g_boxes[(size_t)b * K_TOP + j]
                             : make_float4(0.f, 0.f, 0.f, 0.f);
        bj[tid] = c;
        aj[tid] = (c.z - c.x) * (c.w - c.y);
    }
    __syncthreads();
    if (i >= win) return;

    float4 bi = g_boxes[(size_t)b * K_TOP + i];
    float ai = (bi.z - bi.x) * (bi.w - bi.y);

    unsigned word = 0;
    int j0 = i - w * 32 + 1;         // only j > i
    if (j0 < 0) j0 = 0;
    for (int jj = j0; jj < 32; jj++) {
        float4 c = bj[jj];
        float ltx = fmaxf(bi.x, c.x), lty = fmaxf(bi.y, c.y);
        float rbx = fminf(bi.z, c.z), rby = fminf(bi.w, c.w);
        float iw = fmaxf(rbx - ltx, 0.f), ih = fmaxf(rby - lty, 0.f);
        float inter = iw * ih;
        float iou = inter / (ai + aj[jj] - inter + 1e-12f);  // same expr as ref
        if (iou > NMS_THR) word |= (1u << jj);
    }
    while (word) {
        int jj = __ffs(word) - 1;
        word &= word - 1;
        unsigned pos = atomicAdd(&g_paircnt[b], 1u);
        if (pos < PAIR_CAP)
            g_pairs[b * PAIR_CAP + pos] = ((unsigned)i << 16) | (unsigned)(w * 32 + jj);
    }
}

// -------- K6: sparse-pair NMS resolve + parallel rank scatter ---------------
__global__ void __launch_bounds__(1024, 1)
final_kernel(float4* __restrict__ out) {
    int b = blockIdx.x, tid = threadIdx.x;
    int lane = tid & 31;

    __shared__ unsigned s_pairs[PAIR_CAP];
    __shared__ unsigned s_sorted[PAIR_CAP];
    __shared__ unsigned s_sup[MSCAN / 32];
    __shared__ unsigned s_keepw[MSCAN / 32];
    __shared__ unsigned s_wexcl[MSCAN / 32];
    __shared__ unsigned s_total;

    int n_top = min((int)g_ncand[b], K_TOP);
    int win = min(n_top, MSCAN);
    unsigned np_raw = g_paircnt[b];
    bool ovf = np_raw > PAIR_CAP;
    int np = min(np_raw, (unsigned)PAIR_CAP);

    if (tid < MSCAN / 32) s_sup[tid] = 0u;
    for (int q = tid; q < np; q += 1024) s_pairs[q] = g_pairs[b * PAIR_CAP + q];
    // zero-fill output (tail stays zero)
    if (tid < OUT_N) out[(size_t)b * OUT_N + tid] = make_float4(0.f, 0.f, 0.f, 0.f);
    __syncthreads();

    int nk = 0, start_i = 0;        // defaults = full fallback (ovf path)

    if (!ovf) {
        // rank-sort pairs ascending (keys unique)
        for (int q = tid; q < np; q += 1024) {
            unsigned key = s_pairs[q];
            int rank = 0;
            for (int k = 0; k < np; k++) rank += (s_pairs[k] < key);
            s_sorted[rank] = key;
        }
        __syncthreads();
        // serial resolve over the (tiny) pair list
        if (tid == 0) {
            for (int q = 0; q < np; q++) {
                unsigned p = s_sorted[q];
                unsigned i = p >> 16, j = p & 0xffffu;
                if (!((s_sup[i >> 5] >> (i & 31)) & 1u))
                    s_sup[j >> 5] |= 1u << (j & 31);
            }
        }
        __syncthreads();
        // word-level keep counts + warp scan
        if (tid < MSCAN / 32) {
            unsigned keep = ~s_sup[tid];
            int base = tid * 32;
            if (base >= win) keep = 0u;
            else if (win - base < 32) keep &= (1u << (win - base)) - 1u;
            unsigned cnt = (unsigned)__popc(keep);
            unsigned vv = cnt;
            for (int off = 1; off < 32; off <<= 1) {
                unsigned nb = __shfl_up_sync(0xffffffffu, vv, off);
                if (lane >= off) vv += nb;
            }
            s_keepw[tid] = keep;
            s_wexcl[tid] = vv - cnt;
            if (tid == 31) s_total = vv;
        }
        __syncthreads();
        unsigned kw = s_total;
        // parallel scatter of kept boxes by rank
        if (tid < win) {
            unsigned keep = s_keepw[tid >> 5];
            if ((keep >> (tid & 31)) & 1u) {
                unsigned rank = s_wexcl[tid >> 5] +
                                (unsigned)__popc(keep & ((1u << (tid & 31)) - 1u));
                if (rank < OUT_N)
                    out[(size_t)b * OUT_N + rank] = g_boxes[(size_t)b * K_TOP + tid];
            }
        }
        if (kw >= OUT_N || win >= n_top) return;   // common case: done
        nk = (int)kw;
        start_i = win;
        __syncthreads();
    }

    // ---- fallback: direct block NMS (ovf: from 0; else continue past window)
    float4 acc = make_float4(0.f, 0.f, 0.f, 0.f);
    float accA = 0.f;
    if (tid < nk) {
        acc = out[(size_t)b * OUT_N + tid];
        accA = (acc.z - acc.x) * (acc.w - acc.y);
    }
    for (int i = start_i; i < n_top && nk < OUT_N; i++) {
        float4 c = g_boxes[(size_t)b * K_TOP + i];
        int pred = 0;
        if (tid < nk) {
            float areaC = (c.z - c.x) * (c.w - c.y);
            float ltx = fmaxf(acc.x, c.x), lty = fmaxf(acc.y, c.y);
            float rbx = fminf(acc.z, c.z), rby = fminf(acc.w, c.w);
            float iw = fmaxf(rbx - ltx, 0.f), ih = fmaxf(rby - lty, 0.f);
            float inter = iw * ih;
            float iou = inter / (accA + areaC - inter + 1e-12f);
            pred = (iou > NMS_THR);
        }
        int supp = __syncthreads_or(pred);
        if (!supp) {
            if (tid == nk) {
                acc = c; accA = (c.z - c.x) * (c.w - c.y);
                out[(size_t)b * OUT_N + nk] = c;
            }
            nk++;
        }
    }
}

// ---------------- host launcher ---------------------------------------------
extern "C" void kernel_launch(void* const* d_in, const int* in_sizes, int n_in,
                              void* d_out, int out_size) {
    const float2* scores  = (const float2*)d_in[0];   // (B,N,2) f32
    const float4* deltas  = (const float4*)d_in[1];   // (B,N,4) f32
    const float4* anchors = (const float4*)d_in[2];   // (B,N,4) f32
    const int B = 4;
    const int N = in_sizes[0] / (B * 2);

    void* p0;
    cudaGetSymbolAddress(&p0, g_hist);
    cudaMemsetAsync(p0, 0, sizeof(unsigned) * (size_t)B_MAX * BINS);

    dim3 grid((N + 2047) / 2048, B);
    hist_kernel<<<grid, 256>>>(scores, N);
    select_kernel<<<B, 1024>>>();
    gather_kernel<<<grid, 256>>>(scores, N);
    binsort_decode_kernel<<<dim3(NBT, B), 256>>>(deltas, anchors, N);
    pair_kernel<<<dim3(MSCAN / 32, MSCAN / 128, B), 128>>>();
    final_kernel<<<B, 1024>>>((float4*)d_out);
}

// round 7
// speedup vs baseline: 9.9344x; 1.0544x over previous
#include <cuda_runtime.h>
#include <stdint.h>
#include <math.h>

#define B_MAX     4
#define BINS      262144         // fallback full-range bins: bits >> 12
#define CAND_CAP  8192
#define K_TOP     6000
#define OUT_N     1000
#define NMS_THR   0.7f
#define MSCAN     1024
#define PAIR_CAP  2048
#define BASE_BITS 0x3F666666u    // bits of 0.9f — static prefilter threshold
#define FINE_BINS 8192           // 256-ULP bins above 0.9
#define PRE_CAP   32768          // expected ~26.2K candidates above 0.9

// ---------------- device scratch (static; zero-initialized at load) ---------
__device__ unsigned int        g_fine[B_MAX * FINE_BINS];   // re-zeroed by selectf
__device__ unsigned int        g_cnt[B_MAX];                // re-zeroed by final
__device__ unsigned int        g_fail[B_MAX];               // overwritten each run
__device__ unsigned long long  g_pre[B_MAX * PRE_CAP];
__device__ unsigned int        g_binstart[B_MAX * FINE_BINS];
__device__ unsigned int        g_binfill[B_MAX * FINE_BINS]; // zeroed by selectf
__device__ unsigned long long  g_cand[B_MAX * CAND_CAP];
__device__ unsigned int        g_keythr[B_MAX];
__device__ unsigned int        g_sb[B_MAX], g_ss[B_MAX], g_tn[B_MAX];
__device__ unsigned int        g_ncand[B_MAX];
__device__ unsigned int        g_hist[B_MAX * BINS];        // fallback only; fbz zeroes
__device__ float4              g_boxes[B_MAX * K_TOP];
__device__ unsigned int        g_pairs[B_MAX * PAIR_CAP];
__device__ unsigned int        g_paircnt[B_MAX];            // zeroed by selectf

// ------- K1: single pass — prefilter @0.9 into compact list + fine hist -----
__global__ void prefilter_kernel(const float2* __restrict__ scores, int N) {
    int b = blockIdx.y, tid = threadIdx.x;
    __shared__ unsigned long long st[2048];
    __shared__ unsigned sm_cnt, sm_base;
    if (tid == 0) sm_cnt = 0;
    __syncthreads();

    const float2* p = scores + (size_t)b * N;
    int base = blockIdx.x * 2048;
#pragma unroll
    for (int k = 0; k < 8; k++) {
        int i = base + k * 256 + tid;
        if (i < N) {
            unsigned bits = __float_as_uint(p[i].y);
            if (bits >= BASE_BITS) {
                unsigned bin = (bits - BASE_BITS) >> 8;
                if (bin > FINE_BINS - 1) bin = FINE_BINS - 1;
                atomicAdd(&g_fine[b * FINE_BINS + bin], 1u);
                unsigned s = atomicAdd(&sm_cnt, 1u);
                st[s] = ((unsigned long long)bits << 32) | (unsigned)(~(unsigned)i);
            }
        }
    }
    __syncthreads();
    if (tid == 0) sm_base = atomicAdd(&g_cnt[b], sm_cnt);
    __syncthreads();
    unsigned m = sm_cnt, gb = sm_base;
    for (unsigned k = tid; k < m; k += 256)
        if (gb + k < PRE_CAP) g_pre[(size_t)b * PRE_CAP + gb + k] = st[k];
}

// ------- K2: fine select — threshold bin + bin starts (shfl scans) ----------
__global__ void selectf_kernel() {
    int b = blockIdx.x, tid = threadIdx.x;      // 1024 threads
    int lane = tid & 31, w = tid >> 5;

    unsigned hk[8], pref[8];
    unsigned base_r = (unsigned)tid * 8;        // rev positions: bin = 8191 - r
#pragma unroll
    for (int k = 0; k < 8; k++)
        hk[k] = g_fine[b * FINE_BINS + (FINE_BINS - 1 - (base_r + k))];
    unsigned run = 0;
#pragma unroll
    for (int k = 0; k < 8; k++) { run += hk[k]; pref[k] = run; }

    unsigned incl = run;
    for (int off = 1; off < 32; off <<= 1) {
        unsigned v = __shfl_up_sync(0xffffffffu, incl, off);
        if (lane >= off) incl += v;
    }
    __shared__ unsigned wsum[32], wexcl[32], s_grand;
    if (lane == 31) wsum[w] = incl;
    __syncthreads();
    if (w == 0) {
        unsigned v = wsum[lane], iv = v;
        for (int off = 1; off < 32; off <<= 1) {
            unsigned q = __shfl_up_sync(0xffffffffu, iv, off);
            if (lane >= off) iv += q;
        }
        wexcl[lane] = iv - v;
        if (lane == 31) s_grand = iv;
    }
    __syncthreads();
    unsigned texcl = wexcl[w] + (incl - run);

#pragma unroll
    for (int k = 0; k < 8; k++) {
        unsigned ex = texcl + pref[k] - hk[k];
        unsigned in = texcl + pref[k];
        int bin = FINE_BINS - 1 - (int)(base_r + k);
        g_binstart[b * FINE_BINS + bin] = ex;
        if (ex < K_TOP && in >= K_TOP) {        // exactly one (t,k) if total>=K
            g_keythr[b] = BASE_BITS + ((unsigned)bin << 8);
            g_ncand[b]  = (in > CAND_CAP) ? CAND_CAP : in;
        }
    }
    // restore zeros for next replay / prep this run
#pragma unroll
    for (int k = 0; k < 8; k++) {
        g_fine[b * FINE_BINS + (FINE_BINS - 1 - (base_r + k))] = 0u;
        g_binfill[b * FINE_BINS + base_r + k] = 0u;
    }
    if (tid == 0) {
        unsigned fail = (s_grand < K_TOP) || (g_cnt[b] > PRE_CAP);
        g_fail[b] = fail;
        g_paircnt[b] = 0u;
        if (!fail) { g_sb[b] = BASE_BITS; g_ss[b] = 8; g_tn[b] = FINE_BINS; }
    }
}

// ------- FB0: zero full-range hist (predicated; no-op normally) -------------
__global__ void fbz_kernel() {
    if (!(g_fail[0] | g_fail[1] | g_fail[2] | g_fail[3])) return;
    size_t i0 = (size_t)blockIdx.x * blockDim.x + threadIdx.x;
    for (size_t i = i0; i < (size_t)B_MAX * BINS; i += (size_t)gridDim.x * blockDim.x)
        g_hist[i] = 0u;
}

// ------- FB1: full-range histogram (predicated) -----------------------------
__global__ void fb_hist_kernel(const float2* __restrict__ scores, int N) {
    int b = blockIdx.y;
    if (!g_fail[b]) return;
    const float2* p = scores + (size_t)b * N;
    int base = blockIdx.x * 2048;
#pragma unroll
    for (int k = 0; k < 8; k++) {
        int i = base + k * 256 + threadIdx.x;
        if (i < N)
            atomicAdd(&g_hist[b * BINS + (__float_as_uint(p[i].y) >> 12)], 1u);
    }
}

// ------- FB2: full-range select with top-clamped 1024-bin window ------------
__global__ void fb_select_kernel() {
    int b = blockIdx.x, tid = threadIdx.x;
    if (!g_fail[b]) return;
    const unsigned* h = g_hist + (size_t)b * BINS;

    __shared__ unsigned chunksum[1024];
    __shared__ unsigned sc[1024];
    __shared__ unsigned s_c, s_excl, s_T, s_totT;

    int w = tid >> 5, lane = tid & 31;
    for (int c = w; c < 1024; c += 32) {
        unsigned s = 0;
#pragma unroll
        for (int q = 0; q < 8; q++) s += h[c * 256 + q * 32 + lane];
        for (int off = 16; off; off >>= 1) s += __shfl_down_sync(0xffffffffu, s, off);
        if (lane == 0) chunksum[c] = s;
    }
    __syncthreads();
    unsigned v = chunksum[1023 - tid];
    sc[tid] = v;
    __syncthreads();
    for (int off = 1; off < 1024; off <<= 1) {
        unsigned a = (tid >= off) ? sc[tid - off] : 0u;
        __syncthreads(); sc[tid] += a; __syncthreads();
    }
    unsigned incl = sc[tid], excl = incl - v;
    if (excl < K_TOP && incl >= K_TOP) { s_c = (unsigned)(1023 - tid); s_excl = excl; }
    if (tid == 1023 && incl < K_TOP) { s_c = 0xffffffffu; s_T = 0u; s_totT = incl; }
    __syncthreads();
    if (s_c != 0xffffffffu) {
        unsigned c = s_c, ex0 = s_excl;
        unsigned v2 = (tid < 256) ? h[c * 256 + 255 - tid] : 0u;
        sc[tid] = v2;
        __syncthreads();
        for (int off = 1; off < 1024; off <<= 1) {
            unsigned a = (tid >= off) ? sc[tid - off] : 0u;
            __syncthreads(); sc[tid] += a; __syncthreads();
        }
        if (tid < 256) {
            unsigned i2 = ex0 + sc[tid], e2 = i2 - v2;
            if (e2 < K_TOP && i2 >= K_TOP) { s_T = c * 256 + 255 - (unsigned)tid; s_totT = i2; }
        }
        __syncthreads();
    }
    unsigned T = s_T, totT = s_totT;

    // window [T, T+1024); last bin absorbs everything >= T+1023
    unsigned hb = ((size_t)T + tid < BINS) ? h[T + tid] : 0u;
    sc[tid] = hb;
    __syncthreads();
    for (int off = 512; off; off >>= 1) {
        if (tid < off) sc[tid] += sc[tid + off];
        __syncthreads();
    }
    unsigned Wall = sc[0];
    __syncthreads();
    unsigned v3 = (tid == 1023) ? (totT - Wall + hb) : hb;   // overflow-inclusive
    chunksum[tid] = v3;
    __syncthreads();
    unsigned rv = chunksum[1023 - tid];                       // rev for suffix
    sc[tid] = rv;
    __syncthreads();
    for (int off = 1; off < 1024; off <<= 1) {
        unsigned a = (tid >= off) ? sc[tid - off] : 0u;
        __syncthreads(); sc[tid] += a; __syncthreads();
    }
    g_binstart[b * FINE_BINS + (1023 - tid)] = sc[tid] - rv;
    if (tid == 1023) {
        g_ncand[b] = (totT > CAND_CAP) ? CAND_CAP : totT;
        g_sb[b] = T << 12; g_ss[b] = 12; g_tn[b] = 1024;
    }
}

// ------- FB3: full-range gather into window bins (predicated) ---------------
__global__ void fb_gather_kernel(const float2* __restrict__ scores, int N) {
    int b = blockIdx.y;
    if (!g_fail[b]) return;
    unsigned sb = g_sb[b];             // = T << 12
    const float2* p = scores + (size_t)b * N;
    int base = blockIdx.x * 2048;
#pragma unroll
    for (int k = 0; k < 8; k++) {
        int i = base + k * 256 + threadIdx.x;
        if (i < N) {
            unsigned bits = __float_as_uint(p[i].y);
            if (bits >= sb) {
                unsigned o = (bits - sb) >> 12;
                if (o > 1023) o = 1023;
                unsigned pos = g_binstart[b * FINE_BINS + o] +
                               atomicAdd(&g_binfill[b * FINE_BINS + o], 1u);
                if (pos < CAND_CAP)
                    g_cand[(size_t)b * CAND_CAP + pos] =
                        ((unsigned long long)bits << 32) | (unsigned)(~(unsigned)i);
            }
        }
    }
}

// ------- K3: scatter compact prefiltered list into fine-bin segments --------
__global__ void scatter_kernel() {
    int b = blockIdx.y, tid = threadIdx.x;
    if (g_fail[b]) return;
    unsigned cnt = g_cnt[b]; if (cnt > PRE_CAP) cnt = PRE_CAP;
    unsigned thr = g_keythr[b];
    int i0 = blockIdx.x * 2048;
#pragma unroll
    for (int k = 0; k < 8; k++) {
        unsigned i = (unsigned)(i0 + k * 256 + tid);
        if (i < cnt) {
            unsigned long long key = g_pre[(size_t)b * PRE_CAP + i];
            unsigned bits = (unsigned)(key >> 32);
            if (bits >= thr) {
                unsigned bin = (bits - BASE_BITS) >> 8;
                if (bin > FINE_BINS - 1) bin = FINE_BINS - 1;
                unsigned pos = g_binstart[b * FINE_BINS + bin] +
                               atomicAdd(&g_binfill[b * FINE_BINS + bin], 1u);
                if (pos < CAND_CAP) g_cand[(size_t)b * CAND_CAP + pos] = key;
            }
        }
    }
}

// ------- K4: flat per-candidate rank-within-bin + box decode ----------------
__global__ void ranksort_decode_kernel(const float4* __restrict__ deltas,
                                       const float4* __restrict__ anchors, int N) {
    int b = blockIdx.y;
    unsigned i = blockIdx.x * 256 + threadIdx.x;
    unsigned n = g_ncand[b];
    if (i >= n) return;
    unsigned long long key = g_cand[(size_t)b * CAND_CAP + i];
    unsigned bits = (unsigned)(key >> 32);
    unsigned sb = g_sb[b], ss = g_ss[b], tn = g_tn[b];
    unsigned bin = (bits - sb) >> ss;
    if (bin >= tn) bin = tn - 1;
    unsigned st = g_binstart[b * FINE_BINS + bin];
    unsigned fl = g_binfill[b * FINE_BINS + bin];
    unsigned rank = 0;
    for (unsigned q = 0; q < fl; q++) {
        unsigned sl = st + q;
        if (sl < CAND_CAP) rank += (g_cand[(size_t)b * CAND_CAP + sl] > key);
    }
    unsigned pos = st + rank;
    if (pos < K_TOP) {
        unsigned idx = ~(unsigned)(key & 0xffffffffu);
        size_t off = (size_t)b * N + idx;
        float4 a = anchors[off];
        float4 d = deltas[off];
        float w  = a.z - a.x, h = a.w - a.y;
        float cx = a.x + 0.5f * w + d.x * 0.1f * w;
        float cy = a.y + 0.5f * h + d.y * 0.1f * h;
        float nw = w * expf(d.z * 0.2f);
        float nh = h * expf(d.w * 0.2f);
        float4 bx;
        bx.x = fminf(fmaxf(cx - 0.5f * nw, 0.f), 1.f);
        bx.y = fminf(fmaxf(cy - 0.5f * nh, 0.f), 1.f);
        bx.z = fminf(fmaxf(cx + 0.5f * nw, 0.f), 1.f);
        bx.w = fminf(fmaxf(cy + 0.5f * nh, 0.f), 1.f);
        g_boxes[(size_t)b * K_TOP + pos] = bx;
    }
}

// ------- K5: sparse suppression pairs among first MSCAN candidates ----------
__global__ void pair_kernel() {
    int w     = blockIdx.x;
    int chunk = blockIdx.y;
    int b     = blockIdx.z;
    int tid   = threadIdx.x;
    int i = chunk * 128 + tid;

    int n_top = min((int)g_ncand[b], K_TOP);
    int win = min(n_top, MSCAN);

    __shared__ float4 bj[32];
    __shared__ float  aj[32];
    if (tid < 32) {
        int j = w * 32 + tid;
        float4 c = (j < win) ? g_boxes[(size_t)b * K_TOP + j]
                             : make_float4(0.f, 0.f, 0.f, 0.f);
        bj[tid] = c;
        aj[tid] = (c.z - c.x) * (c.w - c.y);
    }
    __syncthreads();
    if (i >= win) return;

    float4 bi = g_boxes[(size_t)b * K_TOP + i];
    float ai = (bi.z - bi.x) * (bi.w - bi.y);

    unsigned word = 0;
    int j0 = i - w * 32 + 1;
    if (j0 < 0) j0 = 0;
    for (int jj = j0; jj < 32; jj++) {
        float4 c = bj[jj];
        float ltx = fmaxf(bi.x, c.x), lty = fmaxf(bi.y, c.y);
        float rbx = fminf(bi.z, c.z), rby = fminf(bi.w, c.w);
        float iw = fmaxf(rbx - ltx, 0.f), ih = fmaxf(rby - lty, 0.f);
        float inter = iw * ih;
        float iou = inter / (ai + aj[jj] - inter + 1e-12f);
        if (iou > NMS_THR) word |= (1u << jj);
    }
    while (word) {
        int jj = __ffs(word) - 1;
        word &= word - 1;
        unsigned pos = atomicAdd(&g_paircnt[b], 1u);
        if (pos < PAIR_CAP)
            g_pairs[b * PAIR_CAP + pos] = ((unsigned)i << 16) | (unsigned)(w * 32 + jj);
    }
}

// ------- K6: sparse-pair NMS resolve + parallel rank scatter ----------------
__global__ void __launch_bounds__(1024, 1)
final_kernel(float4* __restrict__ out) {
    int b = blockIdx.x, tid = threadIdx.x;
    int lane = tid & 31;

    __shared__ unsigned s_pairs[PAIR_CAP];
    __shared__ unsigned s_sorted[PAIR_CAP];
    __shared__ unsigned s_sup[MSCAN / 32];
    __shared__ unsigned s_keepw[MSCAN / 32];
    __shared__ unsigned s_wexcl[MSCAN / 32];
    __shared__ unsigned s_total;

    int n_top = min((int)g_ncand[b], K_TOP);
    int win = min(n_top, MSCAN);
    unsigned np_raw = g_paircnt[b];
    bool ovf = np_raw > PAIR_CAP;
    int np = min(np_raw, (unsigned)PAIR_CAP);

    if (tid == 0) g_cnt[b] = 0u;                 // restore zero for next replay
    if (tid < MSCAN / 32) s_sup[tid] = 0u;
    for (int q = tid; q < np; q += 1024) s_pairs[q] = g_pairs[b * PAIR_CAP + q];
    if (tid < OUT_N) out[(size_t)b * OUT_N + tid] = make_float4(0.f, 0.f, 0.f, 0.f);
    __syncthreads();

    int nk = 0, start_i = 0;

    if (!ovf) {
        for (int q = tid; q < np; q += 1024) {
            unsigned key = s_pairs[q];
            int rank = 0;
            for (int k = 0; k < np; k++) rank += (s_pairs[k] < key);
            s_sorted[rank] = key;
        }
        __syncthreads();
        if (tid == 0) {
            for (int q = 0; q < np; q++) {
                unsigned p = s_sorted[q];
                unsigned i = p >> 16, j = p & 0xffffu;
                if (!((s_sup[i >> 5] >> (i & 31)) & 1u))
                    s_sup[j >> 5] |= 1u << (j & 31);
            }
        }
        __syncthreads();
        if (tid < MSCAN / 32) {
            unsigned keep = ~s_sup[tid];
            int base = tid * 32;
            if (base >= win) keep = 0u;
            else if (win - base < 32) keep &= (1u << (win - base)) - 1u;
            unsigned cnt = (unsigned)__popc(keep);
            unsigned vv = cnt;
            for (int off = 1; off < 32; off <<= 1) {
                unsigned nb = __shfl_up_sync(0xffffffffu, vv, off);
                if (lane >= off) vv += nb;
            }
            s_keepw[tid] = keep;
            s_wexcl[tid] = vv - cnt;
            if (tid == 31) s_total = vv;
        }
        __syncthreads();
        unsigned kw = s_total;
        if (tid < win) {
            unsigned keep = s_keepw[tid >> 5];
            if ((keep >> (tid & 31)) & 1u) {
                unsigned rank = s_wexcl[tid >> 5] +
                                (unsigned)__popc(keep & ((1u << (tid & 31)) - 1u));
                if (rank < OUT_N)
                    out[(size_t)b * OUT_N + rank] = g_boxes[(size_t)b * K_TOP + tid];
            }
        }
        if (kw >= OUT_N || win >= n_top) return;
        nk = (int)kw;
        start_i = win;
        __syncthreads();
    }

    // fallback: direct block NMS continuation
    float4 acc = make_float4(0.f, 0.f, 0.f, 0.f);
    float accA = 0.f;
    if (tid < nk) {
        acc = out[(size_t)b * OUT_N + tid];
        accA = (acc.z - acc.x) * (acc.w - acc.y);
    }
    for (int i = start_i; i < n_top && nk < OUT_N; i++) {
        float4 c = g_boxes[(size_t)b * K_TOP + i];
        int pred = 0;
        if (tid < nk) {
            float areaC = (c.z - c.x) * (c.w - c.y);
            float ltx = fmaxf(acc.x, c.x), lty = fmaxf(acc.y, c.y);
            float rbx = fminf(acc.z, c.z), rby = fminf(acc.w, c.w);
            float iw = fmaxf(rbx - ltx, 0.f), ih = fmaxf(rby - lty, 0.f);
            float inter = iw * ih;
            float iou = inter / (accA + areaC - inter + 1e-12f);
            pred = (iou > NMS_THR);
        }
        int supp = __syncthreads_or(pred);
        if (!supp) {
            if (tid == nk) {
                acc = c; accA = (c.z - c.x) * (c.w - c.y);
                out[(size_t)b * OUT_N + nk] = c;
            }
            nk++;
        }
    }
}

// ---------------- host launcher ---------------------------------------------
extern "C" void kernel_launch(void* const* d_in, const int* in_sizes, int n_in,
                              void* d_out, int out_size) {
    const float2* scores  = (const float2*)d_in[0];   // (B,N,2) f32
    const float4* deltas  = (const float4*)d_in[1];   // (B,N,4) f32
    const float4* anchors = (const float4*)d_in[2];   // (B,N,4) f32
    const int B = 4;
    const int N = in_sizes[0] / (B * 2);

    dim3 gfull((N + 2047) / 2048, B);
    prefilter_kernel<<<gfull, 256>>>(scores, N);
    selectf_kernel<<<B, 1024>>>();
    fbz_kernel<<<2048, 256>>>();                       // no-op unless fail
    fb_hist_kernel<<<gfull, 256>>>(scores, N);         // no-op unless fail
    fb_select_kernel<<<B, 1024>>>();                   // no-op unless fail
    fb_gather_kernel<<<gfull, 256>>>(scores, N);       // no-op unless fail
    scatter_kernel<<<dim3(PRE_CAP / 2048, B), 256>>>();
    ranksort_decode_kernel<<<dim3(CAND_CAP / 256, B), 256>>>(deltas, anchors, N);
    pair_kernel<<<dim3(MSCAN / 32, MSCAN / 128, B), 128>>>();
    final_kernel<<<B, 1024>>>((float4*)d_out);
}